// round 1
// baseline (speedup 1.0000x reference)
#include <cuda_runtime.h>
#include <math.h>

#define S_LEN 2048
#define BATCH 2
#define DMODEL 768
#define NH 12
#define NKV 4
#define HD 64
#define NREP 3
#define FF 3072
#define NTOK (BATCH * S_LEN)
#define KVD (NKV * HD)

// ---------------- scratch (static device memory, no allocations) ----------------
__device__ float g_hn [NTOK * DMODEL];
__device__ float g_q  [NTOK * DMODEL];
__device__ float g_k  [NTOK * KVD];
__device__ float g_v  [NTOK * KVD];
__device__ float g_ao [NTOK * DMODEL];
__device__ float g_h2 [NTOK * DMODEL];
__device__ float g_cur[NTOK * DMODEL];
__device__ float g_gt [NTOK * FF];
__device__ float g_act[NTOK * FF];

// ---------------- RMSNorm: one block per token ----------------
__global__ void __launch_bounds__(256) rmsnorm_kernel(const float* __restrict__ x,
                                                      const float* __restrict__ w,
                                                      float* __restrict__ out)
{
    int tok = blockIdx.x;
    int tid = threadIdx.x;
    const float* xp = x + (size_t)tok * DMODEL;
    float v0 = xp[tid], v1 = xp[tid + 256], v2 = xp[tid + 512];
    float ss = v0 * v0 + v1 * v1 + v2 * v2;
#pragma unroll
    for (int o = 16; o > 0; o >>= 1) ss += __shfl_xor_sync(0xffffffffu, ss, o);
    __shared__ float red[8];
    if ((tid & 31) == 0) red[tid >> 5] = ss;
    __syncthreads();
    float tot = 0.f;
#pragma unroll
    for (int i = 0; i < 8; i++) tot += red[i];
    float sc = rsqrtf(tot * (1.0f / DMODEL) + 1e-6f);
    float* op = out + (size_t)tok * DMODEL;
    op[tid]       = v0 * sc * w[tid];
    op[tid + 256] = v1 * sc * w[tid + 256];
    op[tid + 512] = v2 * sc * w[tid + 512];
}

// ---------------- RoPE (in place), nh heads of dim 64 ----------------
__global__ void __launch_bounds__(256) rope_kernel(float* __restrict__ t, int nh, int total)
{
    int idx = blockIdx.x * blockDim.x + threadIdx.x;
    if (idx >= total) return;
    int p   = idx & 31;
    int hh  = (idx >> 5) % nh;
    int tok = idx / (32 * nh);
    int s   = tok & (S_LEN - 1);
    // freq = theta^(-2p/64); double pow -> matches numpy float32 table to <=1 ulp
    float freq = (float)pow(10000.0, -(double)p / 32.0);
    float ang = (float)s * freq;
    float c, sn;
    sn = sinf(ang);
    c  = cosf(ang);
    float* base = t + ((size_t)tok * nh + hh) * HD + 2 * p;
    float t0 = base[0], t1 = base[1];
    base[0] = t0 * c - t1 * sn;
    base[1] = t0 * sn + t1 * c;
}

// ---------------- SGEMM 128x128x8, 256 threads, 8x8 microtile ----------------
// MODE 0: C = A@B
// MODE 1: C = A@B + aux        (residual)
// MODE 2: C = silu(aux) * A@B  (SwiGLU combine)
template <int MODE>
__global__ void __launch_bounds__(256) sgemm_kernel(const float* __restrict__ A,
                                                    const float* __restrict__ B,
                                                    float* __restrict__ C,
                                                    const float* __restrict__ aux,
                                                    int M, int N, int K)
{
    __shared__ float As[8][128];
    __shared__ float Bs[8][128];
    int tid = threadIdx.x;
    int tx = tid & 15, ty = tid >> 4;
    int brow = blockIdx.y, bcol = blockIdx.x;
    const float* Ab = A + (size_t)brow * 128 * K;
    const float* Bb = B + (size_t)bcol * 128;

    int ar = tid >> 1, ac = (tid & 1) * 4;
    int brr = tid >> 5, bc = (tid & 31) * 4;

    float acc[8][8] = {};

    for (int k0 = 0; k0 < K; k0 += 8) {
        float4 av = *(const float4*)(Ab + (size_t)ar * K + k0 + ac);
        As[ac + 0][ar] = av.x; As[ac + 1][ar] = av.y;
        As[ac + 2][ar] = av.z; As[ac + 3][ar] = av.w;
        *(float4*)&Bs[brr][bc] = *(const float4*)(Bb + (size_t)(k0 + brr) * N + bc);
        __syncthreads();
#pragma unroll
        for (int kk = 0; kk < 8; kk++) {
            float4 a0 = *(float4*)&As[kk][ty * 4];
            float4 a1 = *(float4*)&As[kk][64 + ty * 4];
            float4 b0 = *(float4*)&Bs[kk][tx * 4];
            float4 b1 = *(float4*)&Bs[kk][64 + tx * 4];
            float a[8] = {a0.x, a0.y, a0.z, a0.w, a1.x, a1.y, a1.z, a1.w};
            float b[8] = {b0.x, b0.y, b0.z, b0.w, b1.x, b1.y, b1.z, b1.w};
#pragma unroll
            for (int i = 0; i < 8; i++)
#pragma unroll
                for (int j = 0; j < 8; j++)
                    acc[i][j] += a[i] * b[j];
        }
        __syncthreads();
    }

#pragma unroll
    for (int i = 0; i < 8; i++) {
        int rloc = (i < 4) ? (ty * 4 + i) : (64 + ty * 4 + i - 4);
        size_t rowoff = (size_t)(brow * 128 + rloc) * N;
#pragma unroll
        for (int jh = 0; jh < 2; jh++) {
            size_t coff = rowoff + bcol * 128 + jh * 64 + tx * 4;
            float e[4];
#pragma unroll
            for (int jj = 0; jj < 4; jj++) {
                float val = acc[i][jh * 4 + jj];
                if (MODE == 1) {
                    val += aux[coff + jj];
                } else if (MODE == 2) {
                    float g = aux[coff + jj];
                    val *= g / (1.0f + __expf(-g));
                }
                e[jj] = val;
            }
            *(float4*)(C + coff) = make_float4(e[0], e[1], e[2], e[3]);
        }
    }
}

// ---------------- fp32 flash attention, 64x64 tiles, causal, GQA ----------------
__global__ void __launch_bounds__(256) attn_kernel(const float* __restrict__ q,
                                                   const float* __restrict__ k,
                                                   const float* __restrict__ v,
                                                   float* __restrict__ out)
{
    __shared__ float Qt[64][64];   // [d][row], pre-scaled by 1/sqrt(HD)
    __shared__ float KP[64][64];   // K as [d][col]; reused as P [row][col]
    __shared__ float Vs[64][64];   // [key][d]

    int tid = threadIdx.x;
    int tx = tid & 15, ty = tid >> 4;
    int qi = blockIdx.x;
    int bh = blockIdx.y;
    int b = bh / NH, h = bh - b * NH;
    int kvh = h / NREP;

    const float* qb = q + ((size_t)(b * S_LEN + qi * 64)) * DMODEL + h * HD;
    const float* kb = k + ((size_t)(b * S_LEN)) * KVD + kvh * HD;
    const float* vb = v + ((size_t)(b * S_LEN)) * KVD + kvh * HD;

    {
        int r = tid >> 2;
        int c0 = (tid & 3) * 16;
#pragma unroll
        for (int it = 0; it < 4; it++) {
            int d = c0 + it * 4;
            float4 qv = *(const float4*)(qb + (size_t)r * DMODEL + d);
            Qt[d + 0][r] = qv.x * 0.125f;
            Qt[d + 1][r] = qv.y * 0.125f;
            Qt[d + 2][r] = qv.z * 0.125f;
            Qt[d + 3][r] = qv.w * 0.125f;
        }
    }

    float o[4][4] = {};
    float m[4], l[4];
#pragma unroll
    for (int i = 0; i < 4; i++) { m[i] = -1e30f; l[i] = 0.f; }

    for (int j = 0; j <= qi; j++) {
        {   // load K (transposed) and V tiles
            int r = tid >> 2;
            int c0 = (tid & 3) * 16;
            const float* krow = kb + (size_t)(j * 64 + r) * KVD;
            const float* vrow = vb + (size_t)(j * 64 + r) * KVD;
#pragma unroll
            for (int it = 0; it < 4; it++) {
                int d = c0 + it * 4;
                float4 kv = *(const float4*)(krow + d);
                KP[d + 0][r] = kv.x; KP[d + 1][r] = kv.y;
                KP[d + 2][r] = kv.z; KP[d + 3][r] = kv.w;
                *(float4*)&Vs[r][d] = *(const float4*)(vrow + d);
            }
        }
        __syncthreads();

        float s[4][4] = {};
#pragma unroll 16
        for (int kk = 0; kk < 64; kk++) {
            float4 a4 = *(float4*)&Qt[kk][ty * 4];
            float4 b4 = *(float4*)&KP[kk][tx * 4];
            float a[4] = {a4.x, a4.y, a4.z, a4.w};
            float bb[4] = {b4.x, b4.y, b4.z, b4.w};
#pragma unroll
            for (int i = 0; i < 4; i++)
#pragma unroll
                for (int jj = 0; jj < 4; jj++)
                    s[i][jj] += a[i] * bb[jj];
        }

        if (j == qi) {
#pragma unroll
            for (int i = 0; i < 4; i++)
#pragma unroll
                for (int jj = 0; jj < 4; jj++)
                    if (tx * 4 + jj > ty * 4 + i) s[i][jj] = -1e30f;
        }
        __syncthreads();   // everyone done reading KP as K

        // online softmax update (row groups of 16 threads share ty)
        float f[4];
#pragma unroll
        for (int i = 0; i < 4; i++) {
            float mt = fmaxf(fmaxf(s[i][0], s[i][1]), fmaxf(s[i][2], s[i][3]));
#pragma unroll
            for (int off = 8; off > 0; off >>= 1)
                mt = fmaxf(mt, __shfl_xor_sync(0xffffffffu, mt, off));
            float mn = fmaxf(m[i], mt);
            f[i] = __expf(m[i] - mn);
            m[i] = mn;
            float rs = 0.f;
#pragma unroll
            for (int jj = 0; jj < 4; jj++) {
                float p = __expf(s[i][jj] - mn);
                s[i][jj] = p;
                rs += p;
            }
#pragma unroll
            for (int off = 8; off > 0; off >>= 1)
                rs += __shfl_xor_sync(0xffffffffu, rs, off);
            l[i] = l[i] * f[i] + rs;
#pragma unroll
            for (int jj = 0; jj < 4; jj++) o[i][jj] *= f[i];
        }

#pragma unroll
        for (int i = 0; i < 4; i++)
#pragma unroll
            for (int jj = 0; jj < 4; jj++)
                KP[ty * 4 + i][tx * 4 + jj] = s[i][jj];
        __syncthreads();

#pragma unroll 16
        for (int cc = 0; cc < 64; cc++) {
            float4 vv = *(float4*)&Vs[cc][tx * 4];
            float pa[4];
#pragma unroll
            for (int i = 0; i < 4; i++) pa[i] = KP[ty * 4 + i][cc];
#pragma unroll
            for (int i = 0; i < 4; i++) {
                o[i][0] += pa[i] * vv.x;
                o[i][1] += pa[i] * vv.y;
                o[i][2] += pa[i] * vv.z;
                o[i][3] += pa[i] * vv.w;
            }
        }
        __syncthreads();
    }

#pragma unroll
    for (int i = 0; i < 4; i++) {
        float inv = 1.0f / l[i];
        int tok = qi * 64 + ty * 4 + i;
        float4 r4 = make_float4(o[i][0] * inv, o[i][1] * inv, o[i][2] * inv, o[i][3] * inv);
        *(float4*)(out + ((size_t)(b * S_LEN + tok)) * DMODEL + h * HD + tx * 4) = r4;
    }
}

// ---------------- orchestration ----------------
extern "C" void kernel_launch(void* const* d_in, const int* in_sizes, int n_in,
                              void* d_out, int out_size)
{
    const float* x   = (const float*)d_in[0];
    const float* Wq  = (const float*)d_in[1];
    const float* Wk  = (const float*)d_in[2];
    const float* Wv  = (const float*)d_in[3];
    const float* Wo  = (const float*)d_in[4];
    const float* anw = (const float*)d_in[5];
    const float* w0  = (const float*)d_in[6];
    const float* w1  = (const float*)d_in[7];
    const float* w2  = (const float*)d_in[8];
    const float* snw = (const float*)d_in[9];
    const float* onw = (const float*)d_in[10];
    float* out = (float*)d_out;

    float *hn, *q, *k, *v, *ao, *h2, *cur, *gt, *act;
    cudaGetSymbolAddress((void**)&hn,  g_hn);
    cudaGetSymbolAddress((void**)&q,   g_q);
    cudaGetSymbolAddress((void**)&k,   g_k);
    cudaGetSymbolAddress((void**)&v,   g_v);
    cudaGetSymbolAddress((void**)&ao,  g_ao);
    cudaGetSymbolAddress((void**)&h2,  g_h2);
    cudaGetSymbolAddress((void**)&cur, g_cur);
    cudaGetSymbolAddress((void**)&gt,  g_gt);
    cudaGetSymbolAddress((void**)&act, g_act);

    dim3 blk(256);
    const float* curin = x;
    for (int l = 0; l < 2; l++) {
        rmsnorm_kernel<<<NTOK, blk>>>(curin, anw + l * DMODEL, hn);

        sgemm_kernel<0><<<dim3(DMODEL / 128, NTOK / 128), blk>>>(
            hn, Wq + (size_t)l * DMODEL * DMODEL, q, nullptr, NTOK, DMODEL, DMODEL);
        sgemm_kernel<0><<<dim3(KVD / 128, NTOK / 128), blk>>>(
            hn, Wk + (size_t)l * DMODEL * KVD, k, nullptr, NTOK, KVD, DMODEL);
        sgemm_kernel<0><<<dim3(KVD / 128, NTOK / 128), blk>>>(
            hn, Wv + (size_t)l * DMODEL * KVD, v, nullptr, NTOK, KVD, DMODEL);

        rope_kernel<<<(NTOK * NH * 32) / 256, blk>>>(q, NH, NTOK * NH * 32);
        rope_kernel<<<(NTOK * NKV * 32) / 256, blk>>>(k, NKV, NTOK * NKV * 32);

        attn_kernel<<<dim3(S_LEN / 64, BATCH * NH), blk>>>(q, k, v, ao);

        sgemm_kernel<1><<<dim3(DMODEL / 128, NTOK / 128), blk>>>(
            ao, Wo + (size_t)l * DMODEL * DMODEL, h2, curin, NTOK, DMODEL, DMODEL);

        rmsnorm_kernel<<<NTOK, blk>>>(h2, snw + l * DMODEL, hn);

        sgemm_kernel<0><<<dim3(FF / 128, NTOK / 128), blk>>>(
            hn, w0 + (size_t)l * DMODEL * FF, gt, nullptr, NTOK, FF, DMODEL);
        sgemm_kernel<2><<<dim3(FF / 128, NTOK / 128), blk>>>(
            hn, w1 + (size_t)l * DMODEL * FF, act, gt, NTOK, FF, DMODEL);
        sgemm_kernel<1><<<dim3(DMODEL / 128, NTOK / 128), blk>>>(
            act, w2 + (size_t)l * FF * DMODEL, cur, h2, NTOK, DMODEL, FF);

        curin = cur;
    }
    rmsnorm_kernel<<<NTOK, blk>>>(curin, onw, out);
}

// round 3
// speedup vs baseline: 1.2092x; 1.2092x over previous
#include <cuda_runtime.h>
#include <math.h>

#define S_LEN 2048
#define BATCH 2
#define DMODEL 768
#define NH 12
#define NKV 4
#define HD 64
#define NREP 3
#define FF 3072
#define NTOK (BATCH * S_LEN)
#define KVD (NKV * HD)
#define QKVN (DMODEL + 2 * KVD)   // 1280

// ---------------- scratch (static device memory, no allocations) ----------------
__device__ float g_hn  [NTOK * DMODEL];
__device__ float g_qkv [NTOK * QKVN];
__device__ float g_ao  [NTOK * DMODEL];
__device__ float g_h2  [NTOK * DMODEL];
__device__ float g_cur [NTOK * DMODEL];
__device__ float g_act [NTOK * FF];
__device__ float g_wqkv[2 * DMODEL * QKVN];
__device__ float g_w01 [2 * DMODEL * 2 * FF];

// ---------------- weight packing (runs once per launch, trivial cost) ----------------
__global__ void __launch_bounds__(256) pack_qkv_kernel(const float* __restrict__ Wq,
                                                       const float* __restrict__ Wk,
                                                       const float* __restrict__ Wv,
                                                       float* __restrict__ out)
{
    int idx = blockIdx.x * blockDim.x + threadIdx.x;  // 2*768*1280
    int c = idx % QKVN;
    int r = (idx / QKVN) % DMODEL;
    int l = idx / (QKVN * DMODEL);
    float v;
    if (c < DMODEL)          v = Wq[((size_t)l * DMODEL + r) * DMODEL + c];
    else if (c < DMODEL+KVD) v = Wk[((size_t)l * DMODEL + r) * KVD + (c - DMODEL)];
    else                     v = Wv[((size_t)l * DMODEL + r) * KVD + (c - DMODEL - KVD)];
    out[idx] = v;
}

__global__ void __launch_bounds__(256) pack_w01_kernel(const float* __restrict__ w0,
                                                       const float* __restrict__ w1,
                                                       float* __restrict__ out)
{
    int idx = blockIdx.x * blockDim.x + threadIdx.x;  // 2*768*6144
    int c = idx % (2 * FF);
    int r = (idx / (2 * FF)) % DMODEL;
    int l = idx / (2 * FF * DMODEL);
    int blk = c >> 7, w = c & 127;
    float v;
    if (w < 64) v = w0[((size_t)l * DMODEL + r) * FF + blk * 64 + w];
    else        v = w1[((size_t)l * DMODEL + r) * FF + blk * 64 + (w - 64)];
    out[idx] = v;
}

// ---------------- RMSNorm: one block per token ----------------
__global__ void __launch_bounds__(256) rmsnorm_kernel(const float* __restrict__ x,
                                                      const float* __restrict__ w,
                                                      float* __restrict__ out)
{
    int tok = blockIdx.x;
    int tid = threadIdx.x;
    const float* xp = x + (size_t)tok * DMODEL;
    float v0 = xp[tid], v1 = xp[tid + 256], v2 = xp[tid + 512];
    float ss = v0 * v0 + v1 * v1 + v2 * v2;
#pragma unroll
    for (int o = 16; o > 0; o >>= 1) ss += __shfl_xor_sync(0xffffffffu, ss, o);
    __shared__ float red[8];
    if ((tid & 31) == 0) red[tid >> 5] = ss;
    __syncthreads();
    float tot = 0.f;
#pragma unroll
    for (int i = 0; i < 8; i++) tot += red[i];
    float sc = rsqrtf(tot * (1.0f / DMODEL) + 1e-6f);
    float* op = out + (size_t)tok * DMODEL;
    op[tid]       = v0 * sc * w[tid];
    op[tid + 256] = v1 * sc * w[tid + 256];
    op[tid + 512] = v2 * sc * w[tid + 512];
}

// ---------------- RoPE (in place, strided rows) ----------------
__global__ void __launch_bounds__(256) rope_kernel(float* __restrict__ t, int nh,
                                                   int rowstride, int total)
{
    int idx = blockIdx.x * blockDim.x + threadIdx.x;
    if (idx >= total) return;
    int p   = idx & 31;
    int hh  = (idx >> 5) % nh;
    int tok = idx / (32 * nh);
    int s   = tok & (S_LEN - 1);
    float freq = (float)pow(10000.0, -(double)p / 32.0);
    float ang = (float)s * freq;
    float sn = sinf(ang), c = cosf(ang);
    float* base = t + (size_t)tok * rowstride + hh * HD + 2 * p;
    float t0 = base[0], t1 = base[1];
    base[0] = t0 * c - t1 * sn;
    base[1] = t0 * sn + t1 * c;
}

// ---------------- SGEMM 128x128x16, double-buffered, 256 threads, 8x8 microtile ----
// MODE 0: C = A@B
// MODE 1: C = A@B + aux
// MODE 3: packed SwiGLU: cols[0:64) of tile = gate (w0), [64:128) = up (w1);
//         writes silu(g)*u to C with row stride N/2.
template <int MODE>
__global__ void __launch_bounds__(256, 2) sgemm_kernel(const float* __restrict__ A,
                                                       const float* __restrict__ B,
                                                       float* __restrict__ C,
                                                       const float* __restrict__ aux,
                                                       int N, int K)
{
    __shared__ float As[2][16][128];
    __shared__ float Bs[2][16][128];
    int tid = threadIdx.x;
    int tx = tid & 15, ty = tid >> 4;
    int brow = blockIdx.y, bcol = blockIdx.x;
    const float* Ab = A + (size_t)brow * 128 * K;
    const float* Bb = B + (size_t)bcol * 128;

    float4 pa[2], pb[2];
    int f0 = tid * 2, f1 = tid * 2 + 1;
    int ar0 = f0 >> 2, ak0 = (f0 & 3) * 4;
    int ar1 = f1 >> 2, ak1 = (f1 & 3) * 4;
    int br0 = f0 >> 5, bc0 = (f0 & 31) * 4;
    int br1 = f1 >> 5, bc1 = (f1 & 31) * 4;

    float acc[8][8] = {};
    int nt = K / 16;

    // prologue load tile 0
    pa[0] = *(const float4*)(Ab + (size_t)ar0 * K + ak0);
    pa[1] = *(const float4*)(Ab + (size_t)ar1 * K + ak1);
    pb[0] = *(const float4*)(Bb + (size_t)br0 * N + bc0);
    pb[1] = *(const float4*)(Bb + (size_t)br1 * N + bc1);
    As[0][ak0 + 0][ar0] = pa[0].x; As[0][ak0 + 1][ar0] = pa[0].y;
    As[0][ak0 + 2][ar0] = pa[0].z; As[0][ak0 + 3][ar0] = pa[0].w;
    As[0][ak1 + 0][ar1] = pa[1].x; As[0][ak1 + 1][ar1] = pa[1].y;
    As[0][ak1 + 2][ar1] = pa[1].z; As[0][ak1 + 3][ar1] = pa[1].w;
    *(float4*)&Bs[0][br0][bc0] = pb[0];
    *(float4*)&Bs[0][br1][bc1] = pb[1];
    __syncthreads();

    for (int t = 0; t < nt; t++) {
        int cur = t & 1;
        if (t + 1 < nt) {
            int k0 = (t + 1) * 16;
            pa[0] = *(const float4*)(Ab + (size_t)ar0 * K + k0 + ak0);
            pa[1] = *(const float4*)(Ab + (size_t)ar1 * K + k0 + ak1);
            pb[0] = *(const float4*)(Bb + (size_t)(k0 + br0) * N + bc0);
            pb[1] = *(const float4*)(Bb + (size_t)(k0 + br1) * N + bc1);
        }
#pragma unroll
        for (int kk = 0; kk < 16; kk++) {
            float4 a0 = *(float4*)&As[cur][kk][ty * 4];
            float4 a1 = *(float4*)&As[cur][kk][64 + ty * 4];
            float4 b0 = *(float4*)&Bs[cur][kk][tx * 4];
            float4 b1 = *(float4*)&Bs[cur][kk][64 + tx * 4];
            float a[8] = {a0.x, a0.y, a0.z, a0.w, a1.x, a1.y, a1.z, a1.w};
            float b[8] = {b0.x, b0.y, b0.z, b0.w, b1.x, b1.y, b1.z, b1.w};
#pragma unroll
            for (int i = 0; i < 8; i++)
#pragma unroll
                for (int j = 0; j < 8; j++)
                    acc[i][j] += a[i] * b[j];
        }
        if (t + 1 < nt) {
            int nxt = cur ^ 1;
            As[nxt][ak0 + 0][ar0] = pa[0].x; As[nxt][ak0 + 1][ar0] = pa[0].y;
            As[nxt][ak0 + 2][ar0] = pa[0].z; As[nxt][ak0 + 3][ar0] = pa[0].w;
            As[nxt][ak1 + 0][ar1] = pa[1].x; As[nxt][ak1 + 1][ar1] = pa[1].y;
            As[nxt][ak1 + 2][ar1] = pa[1].z; As[nxt][ak1 + 3][ar1] = pa[1].w;
            *(float4*)&Bs[nxt][br0][bc0] = pb[0];
            *(float4*)&Bs[nxt][br1][bc1] = pb[1];
            __syncthreads();
        }
    }

#pragma unroll
    for (int i = 0; i < 8; i++) {
        int rloc = (i < 4) ? (ty * 4 + i) : (64 + ty * 4 + i - 4);
        if (MODE == 3) {
            int half = N >> 1;
            size_t coff = (size_t)(brow * 128 + rloc) * half + bcol * 64 + tx * 4;
            float e[4];
#pragma unroll
            for (int jj = 0; jj < 4; jj++) {
                float g = acc[i][jj];
                float u = acc[i][4 + jj];
                e[jj] = u * g / (1.0f + __expf(-g));
            }
            *(float4*)(C + coff) = make_float4(e[0], e[1], e[2], e[3]);
        } else {
            size_t rowoff = (size_t)(brow * 128 + rloc) * N;
#pragma unroll
            for (int jh = 0; jh < 2; jh++) {
                size_t coff = rowoff + bcol * 128 + jh * 64 + tx * 4;
                float e[4];
#pragma unroll
                for (int jj = 0; jj < 4; jj++) {
                    float val = acc[i][jh * 4 + jj];
                    if (MODE == 1) val += aux[coff + jj];
                    e[jj] = val;
                }
                *(float4*)(C + coff) = make_float4(e[0], e[1], e[2], e[3]);
            }
        }
    }
}

// ---------------- fp32 flash attention, 64x64 tiles, causal, GQA, prefetched ------
__global__ void __launch_bounds__(256) attn_kernel(const float* __restrict__ q,
                                                   const float* __restrict__ k,
                                                   const float* __restrict__ v,
                                                   float* __restrict__ out,
                                                   int qs, int kvs, int os)
{
    __shared__ float Qt[64][64];   // [d][row], pre-scaled
    __shared__ float KP[64][64];   // K as [d][col]; reused as P [row][col]
    __shared__ float Vs[64][64];   // [key][d]

    int tid = threadIdx.x;
    int tx = tid & 15, ty = tid >> 4;
    int qi = blockIdx.x;
    int bh = blockIdx.y;
    int b = bh / NH, h = bh - b * NH;
    int kvh = h / NREP;

    const float* qb = q + (size_t)(b * S_LEN + qi * 64) * qs + h * HD;
    const float* kb = k + (size_t)(b * S_LEN) * kvs + kvh * HD;
    const float* vb = v + (size_t)(b * S_LEN) * kvs + kvh * HD;

    int r = tid >> 2;
    int c0 = (tid & 3) * 16;
    {
#pragma unroll
        for (int it = 0; it < 4; it++) {
            int d = c0 + it * 4;
            float4 qv = *(const float4*)(qb + (size_t)r * qs + d);
            Qt[d + 0][r] = qv.x * 0.125f;
            Qt[d + 1][r] = qv.y * 0.125f;
            Qt[d + 2][r] = qv.z * 0.125f;
            Qt[d + 3][r] = qv.w * 0.125f;
        }
    }

    float o[4][4] = {};
    float m[4], l[4];
#pragma unroll
    for (int i = 0; i < 4; i++) { m[i] = -1e30f; l[i] = 0.f; }

    float4 kreg[4], vreg[4];
    {
        const float* krow = kb + (size_t)r * kvs;
        const float* vrow = vb + (size_t)r * kvs;
#pragma unroll
        for (int it = 0; it < 4; it++) {
            kreg[it] = *(const float4*)(krow + c0 + it * 4);
            vreg[it] = *(const float4*)(vrow + c0 + it * 4);
        }
    }

    for (int j = 0; j <= qi; j++) {
#pragma unroll
        for (int it = 0; it < 4; it++) {
            int d = c0 + it * 4;
            KP[d + 0][r] = kreg[it].x; KP[d + 1][r] = kreg[it].y;
            KP[d + 2][r] = kreg[it].z; KP[d + 3][r] = kreg[it].w;
            *(float4*)&Vs[r][d] = vreg[it];
        }
        __syncthreads();

        if (j < qi) {   // prefetch next K/V tile while computing on this one
            const float* krow = kb + (size_t)((j + 1) * 64 + r) * kvs;
            const float* vrow = vb + (size_t)((j + 1) * 64 + r) * kvs;
#pragma unroll
            for (int it = 0; it < 4; it++) {
                kreg[it] = *(const float4*)(krow + c0 + it * 4);
                vreg[it] = *(const float4*)(vrow + c0 + it * 4);
            }
        }

        float s[4][4] = {};
#pragma unroll 16
        for (int kk = 0; kk < 64; kk++) {
            float4 a4 = *(float4*)&Qt[kk][ty * 4];
            float4 b4 = *(float4*)&KP[kk][tx * 4];
            float a[4] = {a4.x, a4.y, a4.z, a4.w};
            float bb[4] = {b4.x, b4.y, b4.z, b4.w};
#pragma unroll
            for (int i = 0; i < 4; i++)
#pragma unroll
                for (int jj = 0; jj < 4; jj++)
                    s[i][jj] += a[i] * bb[jj];
        }

        if (j == qi) {
#pragma unroll
            for (int i = 0; i < 4; i++)
#pragma unroll
                for (int jj = 0; jj < 4; jj++)
                    if (tx * 4 + jj > ty * 4 + i) s[i][jj] = -1e30f;
        }
        __syncthreads();   // done reading KP as K

        float f[4];
#pragma unroll
        for (int i = 0; i < 4; i++) {
            float mt = fmaxf(fmaxf(s[i][0], s[i][1]), fmaxf(s[i][2], s[i][3]));
#pragma unroll
            for (int off = 8; off > 0; off >>= 1)
                mt = fmaxf(mt, __shfl_xor_sync(0xffffffffu, mt, off));
            float mn = fmaxf(m[i], mt);
            f[i] = __expf(m[i] - mn);
            m[i] = mn;
            float rs = 0.f;
#pragma unroll
            for (int jj = 0; jj < 4; jj++) {
                float p = __expf(s[i][jj] - mn);
                s[i][jj] = p;
                rs += p;
            }
#pragma unroll
            for (int off = 8; off > 0; off >>= 1)
                rs += __shfl_xor_sync(0xffffffffu, rs, off);
            l[i] = l[i] * f[i] + rs;
#pragma unroll
            for (int jj = 0; jj < 4; jj++) o[i][jj] *= f[i];
        }

#pragma unroll
        for (int i = 0; i < 4; i++)
#pragma unroll
            for (int jj = 0; jj < 4; jj++)
                KP[ty * 4 + i][tx * 4 + jj] = s[i][jj];
        __syncthreads();

#pragma unroll 16
        for (int cc = 0; cc < 64; cc++) {
            float4 vv = *(float4*)&Vs[cc][tx * 4];
            float pa[4];
#pragma unroll
            for (int i = 0; i < 4; i++) pa[i] = KP[ty * 4 + i][cc];
#pragma unroll
            for (int i = 0; i < 4; i++) {
                o[i][0] += pa[i] * vv.x;
                o[i][1] += pa[i] * vv.y;
                o[i][2] += pa[i] * vv.z;
                o[i][3] += pa[i] * vv.w;
            }
        }
        __syncthreads();
    }

#pragma unroll
    for (int i = 0; i < 4; i++) {
        float inv = 1.0f / l[i];
        int tok = qi * 64 + ty * 4 + i;
        float4 r4 = make_float4(o[i][0] * inv, o[i][1] * inv, o[i][2] * inv, o[i][3] * inv);
        *(float4*)(out + (size_t)(b * S_LEN + tok) * os + h * HD + tx * 4) = r4;
    }
}

// ---------------- orchestration ----------------
extern "C" void kernel_launch(void* const* d_in, const int* in_sizes, int n_in,
                              void* d_out, int out_size)
{
    const float* x   = (const float*)d_in[0];
    const float* Wq  = (const float*)d_in[1];
    const float* Wk  = (const float*)d_in[2];
    const float* Wv  = (const float*)d_in[3];
    const float* Wo  = (const float*)d_in[4];
    const float* anw = (const float*)d_in[5];
    const float* w0  = (const float*)d_in[6];
    const float* w1  = (const float*)d_in[7];
    const float* w2  = (const float*)d_in[8];
    const float* snw = (const float*)d_in[9];
    const float* onw = (const float*)d_in[10];
    float* out = (float*)d_out;

    float *hn, *qkv, *ao, *h2, *cur, *act, *wqkv, *w01;
    cudaGetSymbolAddress((void**)&hn,   g_hn);
    cudaGetSymbolAddress((void**)&qkv,  g_qkv);
    cudaGetSymbolAddress((void**)&ao,   g_ao);
    cudaGetSymbolAddress((void**)&h2,   g_h2);
    cudaGetSymbolAddress((void**)&cur,  g_cur);
    cudaGetSymbolAddress((void**)&act,  g_act);
    cudaGetSymbolAddress((void**)&wqkv, g_wqkv);
    cudaGetSymbolAddress((void**)&w01,  g_w01);

    dim3 blk(256);

    pack_qkv_kernel<<<(2 * DMODEL * QKVN) / 256, blk>>>(Wq, Wk, Wv, wqkv);
    pack_w01_kernel<<<(2 * DMODEL * 2 * FF) / 256, blk>>>(w0, w1, w01);

    const float* curin = x;
    for (int l = 0; l < 2; l++) {
        rmsnorm_kernel<<<NTOK, blk>>>(curin, anw + l * DMODEL, hn);

        sgemm_kernel<0><<<dim3(QKVN / 128, NTOK / 128), blk>>>(
            hn, wqkv + (size_t)l * DMODEL * QKVN, qkv, nullptr, QKVN, DMODEL);

        rope_kernel<<<(NTOK * NH * 32) / 256, blk>>>(qkv, NH, QKVN, NTOK * NH * 32);
        rope_kernel<<<(NTOK * NKV * 32) / 256, blk>>>(qkv + DMODEL, NKV, QKVN, NTOK * NKV * 32);

        attn_kernel<<<dim3(S_LEN / 64, BATCH * NH), blk>>>(
            qkv, qkv + DMODEL, qkv + DMODEL + KVD, ao, QKVN, QKVN, DMODEL);

        sgemm_kernel<1><<<dim3(DMODEL / 128, NTOK / 128), blk>>>(
            ao, Wo + (size_t)l * DMODEL * DMODEL, h2, curin, DMODEL, DMODEL);

        rmsnorm_kernel<<<NTOK, blk>>>(h2, snw + l * DMODEL, hn);

        sgemm_kernel<3><<<dim3((2 * FF) / 128, NTOK / 128), blk>>>(
            hn, w01 + (size_t)l * DMODEL * 2 * FF, act, nullptr, 2 * FF, DMODEL);

        sgemm_kernel<1><<<dim3(DMODEL / 128, NTOK / 128), blk>>>(
            act, w2 + (size_t)l * FF * DMODEL, cur, h2, DMODEL, FF);

        curin = cur;
    }
    rmsnorm_kernel<<<NTOK, blk>>>(curin, onw, out);
}